// round 15
// baseline (speedup 1.0000x reference)
#include <cuda_runtime.h>
#include <cstdint>

#define SEQ   262144
#define BK    16
#define CHUNK 1024          // steps per block (core)
#define NBLK  (SEQ / CHUNK) // 256 blocks
#define BURN  128           // burn-in steps (discarded, state converges)

union F2U { float2 f; unsigned long long u; };
__device__ __forceinline__ float2 ffma2(float2 a, float2 b, float2 c) {
    F2U A, B, C, R; A.f = a; B.f = b; C.f = c;
    asm("fma.rn.f32x2 %0, %1, %2, %3;" : "=l"(R.u) : "l"(A.u), "l"(B.u), "l"(C.u));
    return R.f;
}
__device__ __forceinline__ float tanha(float x) {
    float r; asm("tanh.approx.f32 %0, %1;" : "=f"(r) : "f"(x)); return r;
}
// preact pre-scaled by 0.5 (folded into weights): sigm = 0.5*tanh(x/2)+0.5
__device__ __forceinline__ float sigm_pre(float xh) { return fmaf(tanha(xh), 0.5f, 0.5f); }

__global__ void __launch_bounds__(128, 2) lstm_scan_kernel(
    const float* __restrict__ x,
    const float* __restrict__ w_ih1, const float* __restrict__ w_hh1, const float* __restrict__ b1,
    const float* __restrict__ w_ih2, const float* __restrict__ w_hh2, const float* __restrict__ b2,
    const float* __restrict__ w_p,  const float* __restrict__ b_p,
    float* __restrict__ out)
{
    __shared__ float xring[32][12];                       // 2 superstep blocks of x
    __shared__ __align__(16) float xpart[2][BK][20][4];   // (b1 + w_ih1·x), i/f/o rows pre-scaled 0.5
    __shared__ __align__(16) float apart[2][BK][20][4];   // (b2 + w_ih2·h1), same pre-scale
    __shared__ __align__(16) float h1r[32][24];
    __shared__ __align__(16) float h2r[32][24];

    const int bid  = blockIdx.x;
    const int Beff = (bid == 0) ? 0 : BURN;               // burn-in steps for this block
    const int gbase = bid * CHUNK - Beff;                 // global t of local t=0
    const int NSb  = (CHUNK + Beff) / BK;                 // supersteps this block

    const int tid  = threadIdx.x;
    const int wid  = tid >> 5;
    // Stagger role->SMSP mapping for second-wave CTAs: co-resident pairs are
    // (bid, bid+148) via LUT_classic[bid%148]; without the shift both CTAs put
    // their heavy recurrence warps (roles 0,2) on SMSPs 0,2. Shift balances
    // each SMSP to one heavy + one light warp.
    const int shift = (bid >= 148) ? 1 : 0;
    const int w    = (wid + shift) & 3;                   // ROLE (0=L1,1=L2pre,2=L2,3=aux)
    const int lane = tid & 31;
    const int uc   = (lane < 20) ? lane : 19;

    // ---------------- per-role resident weights ----------------
    float2 wh[4][10];               // role0: w_hh1 rows; role2: w_hh2 rows (gate g, unit uc)
    float2 wi[3][10]; float bb[3];  // role1: w_ih2 rows r = lane + 32q
    int    au[3], ag[3], av[3];
    float2 wx[3][5];  float bx[3];  // role3: w_ih1 rows
    int    xu[3], xg[3], xv[3];
    float  wpv = 0.f;

    if (w == 0 || w == 2) {
        const float* WH = (w == 0) ? w_hh1 : w_hh2;
        #pragma unroll
        for (int g = 0; g < 4; g++) {
            const int r = g * 20 + uc;
            const float sc = (g == 2) ? 1.f : 0.5f;     // fold sigmoid half-scale
            const float2* row = (const float2*)(WH + r * 20);
            #pragma unroll
            for (int k = 0; k < 10; k++) wh[g][k] = make_float2(row[k].x * sc, row[k].y * sc);
        }
    } else if (w == 1) {
        #pragma unroll
        for (int q = 0; q < 3; q++) {
            const int r  = lane + 32 * q;
            const int ok = (r < 80);
            const int rc = ok ? r : 79;
            const int g  = rc / 20;
            const float sc = (g == 2) ? 1.f : 0.5f;
            const float2* row = (const float2*)(w_ih2 + rc * 20);
            #pragma unroll
            for (int k = 0; k < 10; k++) wi[q][k] = make_float2(row[k].x * sc, row[k].y * sc);
            bb[q] = b2[rc] * sc;
            au[q] = rc % 20; ag[q] = g; av[q] = ok;
        }
    } else {
        #pragma unroll
        for (int q = 0; q < 3; q++) {
            const int r  = lane + 32 * q;
            const int ok = (r < 80);
            const int rc = ok ? r : 79;
            const int g  = rc / 20;
            const float sc = (g == 2) ? 1.f : 0.5f;
            const float* row = w_ih1 + rc * 9;
            wx[q][0] = make_float2(row[0] * sc, row[1] * sc);
            wx[q][1] = make_float2(row[2] * sc, row[3] * sc);
            wx[q][2] = make_float2(row[4] * sc, row[5] * sc);
            wx[q][3] = make_float2(row[6] * sc, row[7] * sc);
            wx[q][4] = make_float2(row[8] * sc, 0.f);
            bx[q] = b1[rc] * sc;
            xu[q] = rc % 20; xg[q] = g; xv[q] = ok;
        }
        if (lane < 20) wpv = w_p[lane];
    }
    const float bpv = b_p[0];

    // ---------------- zero rings ----------------
    for (int i = tid; i < 32 * 24; i += 128) { ((float*)h1r)[i] = 0.f; ((float*)h2r)[i] = 0.f; }
    for (int i = tid; i < 32 * 12; i += 128) ((float*)xring)[i] = 0.f;
    __syncthreads();

    // ---------------- prologue: x local blocks 0,1 then xpart block 0 ----------------
    if (w == 3) {
        #pragma unroll
        for (int bb2 = 0; bb2 < 2; bb2++) {
            const float* src = x + (gbase + bb2 * BK) * 9;
            #pragma unroll
            for (int i = 0; i < 5; i++) {
                const int idx = lane + 32 * i;
                if (idx < 144) {
                    const float v = src[idx];
                    const int st = idx / 9, k = idx - st * 9;
                    xring[bb2 * 16 + st][k] = v;
                }
            }
        }
        __syncwarp();
        #pragma unroll 1
        for (int j = 0; j < BK; j++) {
            const float2* xp = (const float2*)xring[j];
            float2 X0 = xp[0], X1 = xp[1], X2 = xp[2], X3 = xp[3], X4 = xp[4];
            #pragma unroll
            for (int q = 0; q < 3; q++) {
                float2 a = make_float2(bx[q], 0.f);
                a = ffma2(wx[q][0], X0, a); a = ffma2(wx[q][1], X1, a);
                a = ffma2(wx[q][2], X2, a); a = ffma2(wx[q][3], X3, a);
                a = ffma2(wx[q][4], X4, a);
                if (xv[q]) xpart[0][j][xu[q]][xg[q]] = a.x + a.y;
            }
        }
    }
    __syncthreads();

    float cst = 0.f;   // cell state (role0: c1, role2: c2)
    const float2 ONE = make_float2(1.f, 1.f);

    // ================= main superstep loop =================
    #pragma unroll 1
    for (int s = 0; s <= NSb + 2; s++) {
        if (w == 0) {
            // -------- L1 core: block s --------
            if (s < NSb) {
                const int t0 = s * BK;
                const int sl = s & 1;
                #pragma unroll 2
                for (int j = 0; j < BK; j++) {
                    const int t = t0 + j;
                    const float4 xp = *((const float4*)&xpart[sl][j][uc][0]);
                    const float4* hp = (const float4*)h1r[(t + 31) & 31];
                    float2 e0 = make_float2(xp.x, 0.f), e1 = make_float2(xp.y, 0.f);
                    float2 e2 = make_float2(xp.z, 0.f), e3 = make_float2(xp.w, 0.f);
                    float2 o0 = make_float2(0.f, 0.f), o1 = o0, o2 = o0, o3 = o0;
                    #pragma unroll
                    for (int k4 = 0; k4 < 5; k4++) {
                        const float4 hv = hp[k4];
                        const float2 a = make_float2(hv.x, hv.y);
                        const float2 b = make_float2(hv.z, hv.w);
                        e0 = ffma2(wh[0][2*k4], a, e0); e1 = ffma2(wh[1][2*k4], a, e1);
                        e2 = ffma2(wh[2][2*k4], a, e2); e3 = ffma2(wh[3][2*k4], a, e3);
                        o0 = ffma2(wh[0][2*k4+1], b, o0); o1 = ffma2(wh[1][2*k4+1], b, o1);
                        o2 = ffma2(wh[2][2*k4+1], b, o2); o3 = ffma2(wh[3][2*k4+1], b, o3);
                    }
                    e0 = ffma2(ONE, o0, e0); e1 = ffma2(ONE, o1, e1);
                    e2 = ffma2(ONE, o2, e2); e3 = ffma2(ONE, o3, e3);
                    const float si = sigm_pre(e0.x + e0.y);
                    const float sf = sigm_pre(e1.x + e1.y);
                    const float sg = tanha(e2.x + e2.y);
                    const float so = sigm_pre(e3.x + e3.y);
                    cst = fmaf(sf, cst, si * sg);
                    const float h = so * tanha(cst);
                    if (lane < 20) h1r[t & 31][lane] = h;
                    __syncwarp();
                }
            }
        } else if (w == 1) {
            // -------- L2 pre (w_ih2·h1 + b2): block s-1 --------
            if (s >= 1 && s <= NSb) {
                const int b = s - 1;
                const int t0 = b * BK;
                const int sl = b & 1;
                #pragma unroll 2
                for (int j = 0; j < BK; j++) {
                    const float4* hp = (const float4*)h1r[(t0 + j) & 31];
                    float2 A0 = make_float2(bb[0], 0.f), B0 = make_float2(0.f, 0.f);
                    float2 A1 = make_float2(bb[1], 0.f), B1 = B0;
                    float2 A2 = make_float2(bb[2], 0.f), B2 = B0;
                    #pragma unroll
                    for (int k4 = 0; k4 < 5; k4++) {
                        const float4 hv = hp[k4];
                        const float2 a = make_float2(hv.x, hv.y);
                        const float2 b2v = make_float2(hv.z, hv.w);
                        A0 = ffma2(wi[0][2*k4], a, A0); A1 = ffma2(wi[1][2*k4], a, A1); A2 = ffma2(wi[2][2*k4], a, A2);
                        B0 = ffma2(wi[0][2*k4+1], b2v, B0); B1 = ffma2(wi[1][2*k4+1], b2v, B1); B2 = ffma2(wi[2][2*k4+1], b2v, B2);
                    }
                    A0 = ffma2(ONE, B0, A0); A1 = ffma2(ONE, B1, A1); A2 = ffma2(ONE, B2, A2);
                    apart[sl][j][au[0]][ag[0]] = A0.x + A0.y;
                    apart[sl][j][au[1]][ag[1]] = A1.x + A1.y;
                    if (av[2]) apart[sl][j][au[2]][ag[2]] = A2.x + A2.y;
                }
            }
        } else if (w == 2) {
            // -------- L2 core: block s-2 --------
            if (s >= 2 && s <= NSb + 1) {
                const int b = s - 2;
                const int t0 = b * BK;
                const int sl = b & 1;
                #pragma unroll 2
                for (int j = 0; j < BK; j++) {
                    const int t = t0 + j;
                    const float4 ap = *((const float4*)&apart[sl][j][uc][0]);
                    const float4* hp = (const float4*)h2r[(t + 31) & 31];
                    float2 e0 = make_float2(ap.x, 0.f), e1 = make_float2(ap.y, 0.f);
                    float2 e2 = make_float2(ap.z, 0.f), e3 = make_float2(ap.w, 0.f);
                    float2 o0 = make_float2(0.f, 0.f), o1 = o0, o2 = o0, o3 = o0;
                    #pragma unroll
                    for (int k4 = 0; k4 < 5; k4++) {
                        const float4 hv = hp[k4];
                        const float2 a = make_float2(hv.x, hv.y);
                        const float2 b2v = make_float2(hv.z, hv.w);
                        e0 = ffma2(wh[0][2*k4], a, e0); e1 = ffma2(wh[1][2*k4], a, e1);
                        e2 = ffma2(wh[2][2*k4], a, e2); e3 = ffma2(wh[3][2*k4], a, e3);
                        o0 = ffma2(wh[0][2*k4+1], b2v, o0); o1 = ffma2(wh[1][2*k4+1], b2v, o1);
                        o2 = ffma2(wh[2][2*k4+1], b2v, o2); o3 = ffma2(wh[3][2*k4+1], b2v, o3);
                    }
                    e0 = ffma2(ONE, o0, e0); e1 = ffma2(ONE, o1, e1);
                    e2 = ffma2(ONE, o2, e2); e3 = ffma2(ONE, o3, e3);
                    const float si = sigm_pre(e0.x + e0.y);
                    const float sf = sigm_pre(e1.x + e1.y);
                    const float sg = tanha(e2.x + e2.y);
                    const float so = sigm_pre(e3.x + e3.y);
                    cst = fmaf(sf, cst, si * sg);
                    const float h = so * tanha(cst);
                    if (lane < 20) h2r[t & 31][lane] = h;
                    __syncwarp();
                }
            }
        } else {
            // -------- role3: x load (block s+2), xpart (block s+1), proj (block s-3) --------
            if (s + 2 <= NSb - 1) {
                const int b2v = s + 2;
                const float* src = x + (gbase + b2v * BK) * 9;
                #pragma unroll
                for (int i = 0; i < 5; i++) {
                    const int idx = lane + 32 * i;
                    if (idx < 144) {
                        const float v = __ldg(&src[idx]);
                        const int st = idx / 9, k = idx - st * 9;
                        xring[(b2v & 1) * 16 + st][k] = v;
                    }
                }
            }
            if (s + 1 <= NSb - 1) {
                const int bp = s + 1;
                const int xb = (bp & 1) * 16;
                const int sl = bp & 1;
                #pragma unroll 2
                for (int j = 0; j < BK; j++) {
                    const float2* xp = (const float2*)xring[xb + j];
                    const float2 X0 = xp[0], X1 = xp[1], X2 = xp[2], X3 = xp[3], X4 = xp[4];
                    #pragma unroll
                    for (int q = 0; q < 3; q++) {
                        float2 a = make_float2(bx[q], 0.f);
                        float2 o = make_float2(0.f, 0.f);
                        a = ffma2(wx[q][0], X0, a); o = ffma2(wx[q][1], X1, o);
                        a = ffma2(wx[q][2], X2, a); o = ffma2(wx[q][3], X3, o);
                        a = ffma2(wx[q][4], X4, a);
                        a = ffma2(ONE, o, a);
                        if (xv[q]) xpart[sl][j][xu[q]][xg[q]] = a.x + a.y;
                    }
                }
            }
            if (s >= 3) {
                const int b = s - 3;
                const int t0 = b * BK;
                #pragma unroll 2
                for (int j = 0; j < BK; j++) {
                    const int t = t0 + j;
                    const float hv = (lane < 20) ? h2r[t & 31][lane] : 0.f;
                    float p = wpv * hv;
                    #pragma unroll
                    for (int o = 16; o; o >>= 1) p += __shfl_down_sync(0xffffffffu, p, o);
                    if (lane == 0 && t >= Beff) out[gbase + t] = p + bpv;  // skip burn-in
                }
            }
        }
        __syncthreads();
    }
}

extern "C" void kernel_launch(void* const* d_in, const int* in_sizes, int n_in,
                              void* d_out, int out_size) {
    (void)in_sizes; (void)n_in; (void)out_size;
    lstm_scan_kernel<<<NBLK, 128>>>(
        (const float*)d_in[0],
        (const float*)d_in[1], (const float*)d_in[2], (const float*)d_in[3],
        (const float*)d_in[4], (const float*)d_in[5], (const float*)d_in[6],
        (const float*)d_in[7], (const float*)d_in[8],
        (float*)d_out);
}

// round 16
// speedup vs baseline: 1.0704x; 1.0704x over previous
#include <cuda_runtime.h>
#include <cstdint>

#define SEQ   262144
#define BK    16
#define CHUNK 512           // steps per block (core)
#define NBLK  (SEQ / CHUNK) // 512 blocks
#define BURN  128           // burn-in steps (discarded, state converges)

union F2U { float2 f; unsigned long long u; };
__device__ __forceinline__ float2 ffma2(float2 a, float2 b, float2 c) {
    F2U A, B, C, R; A.f = a; B.f = b; C.f = c;
    asm("fma.rn.f32x2 %0, %1, %2, %3;" : "=l"(R.u) : "l"(A.u), "l"(B.u), "l"(C.u));
    return R.f;
}
__device__ __forceinline__ float tanha(float x) {
    float r; asm("tanh.approx.f32 %0, %1;" : "=f"(r) : "f"(x)); return r;
}
// preact pre-scaled by 0.5 (folded into weights): sigm = 0.5*tanh(x/2)+0.5
__device__ __forceinline__ float sigm_pre(float xh) { return fmaf(tanha(xh), 0.5f, 0.5f); }

__global__ void __launch_bounds__(64, 4) lstm_scan_kernel(
    const float* __restrict__ x,
    const float* __restrict__ w_ih1, const float* __restrict__ w_hh1, const float* __restrict__ b1,
    const float* __restrict__ w_ih2, const float* __restrict__ w_hh2, const float* __restrict__ b2,
    const float* __restrict__ w_p,  const float* __restrict__ b_p,
    float* __restrict__ out)
{
    __shared__ float xring[32][12];                       // 2 superstep blocks of x
    __shared__ __align__(16) float xpart[2][BK][20][4];   // (b1 + w_ih1·x), i/f/o rows pre-scaled 0.5
    __shared__ __align__(16) float apart[2][BK][20][4];   // (b2 + w_ih2·h1), same pre-scale
    __shared__ __align__(16) float h1r[32][24];
    __shared__ __align__(16) float h2r[32][24];

    const int bid  = blockIdx.x;
    const int Beff = (bid == 0) ? 0 : BURN;               // burn-in steps for this block
    const int gbase = bid * CHUNK - Beff;                 // global t of local t=0
    const int NSb  = (CHUNK + Beff) / BK;                 // supersteps this block

    const int tid  = threadIdx.x;
    const int w    = tid >> 5;                            // 0 = warp A (L1+L2pre), 1 = warp B (L2+aux)
    const int lane = tid & 31;
    const int uc   = (lane < 20) ? lane : 19;

    // ---------------- per-warp resident weights ----------------
    float2 wh[4][10];               // A: w_hh1 rows; B: w_hh2 rows (gate g, unit uc)
    float2 wi[3][10]; float bb[3];  // A: w_ih2 rows r = lane + 32q  (L2 pre)
    int    au[3], ag[3], av[3];
    float2 wx[3][5];  float bx[3];  // B: w_ih1 rows (xpart)
    int    xu[3], xg[3], xv[3];
    float  wpv = 0.f;

    {
        const float* WH = (w == 0) ? w_hh1 : w_hh2;
        #pragma unroll
        for (int g = 0; g < 4; g++) {
            const int r = g * 20 + uc;
            const float sc = (g == 2) ? 1.f : 0.5f;     // fold sigmoid half-scale
            const float2* row = (const float2*)(WH + r * 20);
            #pragma unroll
            for (int k = 0; k < 10; k++) wh[g][k] = make_float2(row[k].x * sc, row[k].y * sc);
        }
    }
    if (w == 0) {
        #pragma unroll
        for (int q = 0; q < 3; q++) {
            const int r  = lane + 32 * q;
            const int ok = (r < 80);
            const int rc = ok ? r : 79;
            const int g  = rc / 20;
            const float sc = (g == 2) ? 1.f : 0.5f;
            const float2* row = (const float2*)(w_ih2 + rc * 20);
            #pragma unroll
            for (int k = 0; k < 10; k++) wi[q][k] = make_float2(row[k].x * sc, row[k].y * sc);
            bb[q] = b2[rc] * sc;
            au[q] = rc % 20; ag[q] = g; av[q] = ok;
        }
    } else {
        #pragma unroll
        for (int q = 0; q < 3; q++) {
            const int r  = lane + 32 * q;
            const int ok = (r < 80);
            const int rc = ok ? r : 79;
            const int g  = rc / 20;
            const float sc = (g == 2) ? 1.f : 0.5f;
            const float* row = w_ih1 + rc * 9;
            wx[q][0] = make_float2(row[0] * sc, row[1] * sc);
            wx[q][1] = make_float2(row[2] * sc, row[3] * sc);
            wx[q][2] = make_float2(row[4] * sc, row[5] * sc);
            wx[q][3] = make_float2(row[6] * sc, row[7] * sc);
            wx[q][4] = make_float2(row[8] * sc, 0.f);
            bx[q] = b1[rc] * sc;
            xu[q] = rc % 20; xg[q] = g; xv[q] = ok;
        }
        if (lane < 20) wpv = w_p[lane];
    }
    const float bpv = b_p[0];

    // ---------------- zero rings ----------------
    for (int i = tid; i < 32 * 24; i += 64) { ((float*)h1r)[i] = 0.f; ((float*)h2r)[i] = 0.f; }
    for (int i = tid; i < 32 * 12; i += 64) ((float*)xring)[i] = 0.f;
    __syncthreads();

    // ---------------- prologue (warp B): x blocks 0,1 then xpart block 0 ----------------
    if (w == 1) {
        #pragma unroll
        for (int bb2 = 0; bb2 < 2; bb2++) {
            const float* src = x + (gbase + bb2 * BK) * 9;
            #pragma unroll
            for (int i = 0; i < 5; i++) {
                const int idx = lane + 32 * i;
                if (idx < 144) {
                    const float v = src[idx];
                    const int st = idx / 9, k = idx - st * 9;
                    xring[bb2 * 16 + st][k] = v;
                }
            }
        }
        __syncwarp();
        #pragma unroll 1
        for (int j = 0; j < BK; j++) {
            const float2* xp = (const float2*)xring[j];
            float2 X0 = xp[0], X1 = xp[1], X2 = xp[2], X3 = xp[3], X4 = xp[4];
            #pragma unroll
            for (int q = 0; q < 3; q++) {
                float2 a = make_float2(bx[q], 0.f);
                a = ffma2(wx[q][0], X0, a); a = ffma2(wx[q][1], X1, a);
                a = ffma2(wx[q][2], X2, a); a = ffma2(wx[q][3], X3, a);
                a = ffma2(wx[q][4], X4, a);
                if (xv[q]) xpart[0][j][xu[q]][xg[q]] = a.x + a.y;
            }
        }
    }
    __syncthreads();

    float cst = 0.f;   // cell state (A: c1, B: c2)
    const float2 ONE = make_float2(1.f, 1.f);

    // ================= main superstep loop =================
    #pragma unroll 1
    for (int s = 0; s <= NSb + 2; s++) {
        if (w == 0) {
            // ======== warp A ========
            // -------- L1 core: block s --------
            if (s < NSb) {
                const int t0 = s * BK;
                const int sl = s & 1;
                #pragma unroll 2
                for (int j = 0; j < BK; j++) {
                    const int t = t0 + j;
                    const float4 xp = *((const float4*)&xpart[sl][j][uc][0]);
                    const float4* hp = (const float4*)h1r[(t + 31) & 31];
                    float2 e0 = make_float2(xp.x, 0.f), e1 = make_float2(xp.y, 0.f);
                    float2 e2 = make_float2(xp.z, 0.f), e3 = make_float2(xp.w, 0.f);
                    float2 o0 = make_float2(0.f, 0.f), o1 = o0, o2 = o0, o3 = o0;
                    #pragma unroll
                    for (int k4 = 0; k4 < 5; k4++) {
                        const float4 hv = hp[k4];
                        const float2 a = make_float2(hv.x, hv.y);
                        const float2 b = make_float2(hv.z, hv.w);
                        e0 = ffma2(wh[0][2*k4], a, e0); e1 = ffma2(wh[1][2*k4], a, e1);
                        e2 = ffma2(wh[2][2*k4], a, e2); e3 = ffma2(wh[3][2*k4], a, e3);
                        o0 = ffma2(wh[0][2*k4+1], b, o0); o1 = ffma2(wh[1][2*k4+1], b, o1);
                        o2 = ffma2(wh[2][2*k4+1], b, o2); o3 = ffma2(wh[3][2*k4+1], b, o3);
                    }
                    e0 = ffma2(ONE, o0, e0); e1 = ffma2(ONE, o1, e1);
                    e2 = ffma2(ONE, o2, e2); e3 = ffma2(ONE, o3, e3);
                    const float si = sigm_pre(e0.x + e0.y);
                    const float sf = sigm_pre(e1.x + e1.y);
                    const float sg = tanha(e2.x + e2.y);
                    const float so = sigm_pre(e3.x + e3.y);
                    cst = fmaf(sf, cst, si * sg);
                    const float h = so * tanha(cst);
                    if (lane < 20) h1r[t & 31][lane] = h;
                    __syncwarp();
                }
            }
            // -------- L2 pre (w_ih2·h1 + b2): block s-1 --------
            if (s >= 1 && s <= NSb) {
                const int b = s - 1;
                const int t0 = b * BK;
                const int sl = b & 1;
                #pragma unroll 2
                for (int j = 0; j < BK; j++) {
                    const float4* hp = (const float4*)h1r[(t0 + j) & 31];
                    float2 A0 = make_float2(bb[0], 0.f), B0 = make_float2(0.f, 0.f);
                    float2 A1 = make_float2(bb[1], 0.f), B1 = B0;
                    float2 A2 = make_float2(bb[2], 0.f), B2 = B0;
                    #pragma unroll
                    for (int k4 = 0; k4 < 5; k4++) {
                        const float4 hv = hp[k4];
                        const float2 a = make_float2(hv.x, hv.y);
                        const float2 b2v = make_float2(hv.z, hv.w);
                        A0 = ffma2(wi[0][2*k4], a, A0); A1 = ffma2(wi[1][2*k4], a, A1); A2 = ffma2(wi[2][2*k4], a, A2);
                        B0 = ffma2(wi[0][2*k4+1], b2v, B0); B1 = ffma2(wi[1][2*k4+1], b2v, B1); B2 = ffma2(wi[2][2*k4+1], b2v, B2);
                    }
                    A0 = ffma2(ONE, B0, A0); A1 = ffma2(ONE, B1, A1); A2 = ffma2(ONE, B2, A2);
                    apart[sl][j][au[0]][ag[0]] = A0.x + A0.y;
                    apart[sl][j][au[1]][ag[1]] = A1.x + A1.y;
                    if (av[2]) apart[sl][j][au[2]][ag[2]] = A2.x + A2.y;
                }
            }
        } else {
            // ======== warp B ========
            // -------- issue x loads for block s+2 early (latency hides under L2 core) --------
            float xv5[5];
            const bool doX = (s + 2 <= NSb - 1);
            if (doX) {
                const float* src = x + (gbase + (s + 2) * BK) * 9;
                #pragma unroll
                for (int i = 0; i < 5; i++) {
                    const int idx = lane + 32 * i;
                    xv5[i] = (idx < 144) ? __ldg(&src[idx]) : 0.f;
                }
            }
            // -------- L2 core: block s-2 --------
            if (s >= 2 && s <= NSb + 1) {
                const int b = s - 2;
                const int t0 = b * BK;
                const int sl = b & 1;
                #pragma unroll 2
                for (int j = 0; j < BK; j++) {
                    const int t = t0 + j;
                    const float4 ap = *((const float4*)&apart[sl][j][uc][0]);
                    const float4* hp = (const float4*)h2r[(t + 31) & 31];
                    float2 e0 = make_float2(ap.x, 0.f), e1 = make_float2(ap.y, 0.f);
                    float2 e2 = make_float2(ap.z, 0.f), e3 = make_float2(ap.w, 0.f);
                    float2 o0 = make_float2(0.f, 0.f), o1 = o0, o2 = o0, o3 = o0;
                    #pragma unroll
                    for (int k4 = 0; k4 < 5; k4++) {
                        const float4 hv = hp[k4];
                        const float2 a = make_float2(hv.x, hv.y);
                        const float2 b2v = make_float2(hv.z, hv.w);
                        e0 = ffma2(wh[0][2*k4], a, e0); e1 = ffma2(wh[1][2*k4], a, e1);
                        e2 = ffma2(wh[2][2*k4], a, e2); e3 = ffma2(wh[3][2*k4], a, e3);
                        o0 = ffma2(wh[0][2*k4+1], b2v, o0); o1 = ffma2(wh[1][2*k4+1], b2v, o1);
                        o2 = ffma2(wh[2][2*k4+1], b2v, o2); o3 = ffma2(wh[3][2*k4+1], b2v, o3);
                    }
                    e0 = ffma2(ONE, o0, e0); e1 = ffma2(ONE, o1, e1);
                    e2 = ffma2(ONE, o2, e2); e3 = ffma2(ONE, o3, e3);
                    const float si = sigm_pre(e0.x + e0.y);
                    const float sf = sigm_pre(e1.x + e1.y);
                    const float sg = tanha(e2.x + e2.y);
                    const float so = sigm_pre(e3.x + e3.y);
                    cst = fmaf(sf, cst, si * sg);
                    const float h = so * tanha(cst);
                    if (lane < 20) h2r[t & 31][lane] = h;
                    __syncwarp();
                }
            }
            // -------- store x block s+2 into ring --------
            if (doX) {
                const int xb = ((s + 2) & 1) * 16;
                #pragma unroll
                for (int i = 0; i < 5; i++) {
                    const int idx = lane + 32 * i;
                    if (idx < 144) {
                        const int st = idx / 9, k = idx - st * 9;
                        xring[xb + st][k] = xv5[i];
                    }
                }
                __syncwarp();
            }
            // -------- xpart block s+1 --------
            if (s + 1 <= NSb - 1) {
                const int bp = s + 1;
                const int xb = (bp & 1) * 16;
                const int sl = bp & 1;
                #pragma unroll 2
                for (int j = 0; j < BK; j++) {
                    const float2* xp = (const float2*)xring[xb + j];
                    const float2 X0 = xp[0], X1 = xp[1], X2 = xp[2], X3 = xp[3], X4 = xp[4];
                    #pragma unroll
                    for (int q = 0; q < 3; q++) {
                        float2 a = make_float2(bx[q], 0.f);
                        float2 o = make_float2(0.f, 0.f);
                        a = ffma2(wx[q][0], X0, a); o = ffma2(wx[q][1], X1, o);
                        a = ffma2(wx[q][2], X2, a); o = ffma2(wx[q][3], X3, o);
                        a = ffma2(wx[q][4], X4, a);
                        a = ffma2(ONE, o, a);
                        if (xv[q]) xpart[sl][j][xu[q]][xg[q]] = a.x + a.y;
                    }
                }
            }
            // -------- projection block s-3 --------
            if (s >= 3) {
                const int b = s - 3;
                const int t0 = b * BK;
                #pragma unroll 2
                for (int j = 0; j < BK; j++) {
                    const int t = t0 + j;
                    const float hv = (lane < 20) ? h2r[t & 31][lane] : 0.f;
                    float p = wpv * hv;
                    #pragma unroll
                    for (int o = 16; o; o >>= 1) p += __shfl_down_sync(0xffffffffu, p, o);
                    if (lane == 0 && t >= Beff) out[gbase + t] = p + bpv;  // skip burn-in
                }
            }
        }
        __syncthreads();
    }
}

extern "C" void kernel_launch(void* const* d_in, const int* in_sizes, int n_in,
                              void* d_out, int out_size) {
    (void)in_sizes; (void)n_in; (void)out_size;
    lstm_scan_kernel<<<NBLK, 64>>>(
        (const float*)d_in[0],
        (const float*)d_in[1], (const float*)d_in[2], (const float*)d_in[3],
        (const float*)d_in[4], (const float*)d_in[5], (const float*)d_in[6],
        (const float*)d_in[7], (const float*)d_in[8],
        (float*)d_out);
}